// round 13
// baseline (speedup 1.0000x reference)
#include <cuda_runtime.h>
#include <cuda_bf16.h>
#include <math.h>

#define Bsz 8
#define Lseq 2048
#define Dd 128
#define NROWS (Bsz * Lseq)
#define BLD (NROWS * Dd)
#define BDD (Bsz * Dd * Dd)
#define CC 16
#define NCH (Lseq / CC)            // 128
#define NBC (Bsz * NCH)            // 1024

__device__ float g_qkv[NROWS * 512];
__device__ float g_g  [NROWS * 256];
__device__ float g_pk [NROWS * 640];
__device__ float g_res[NROWS * Dd];
__device__ float g_out[NROWS * Dd];
__device__ float g_ol [NROWS * Dd];
__device__ float g_kap[NBC * CC * Dd];
__device__ float g_m1 [NBC * CC * Dd];
__device__ float g_m2 [NBC * CC * Dd];
__device__ float g_lm [NBC * CC * Dd];
__device__ float g_pt [NBC * 512];        // phi[256] | theta[256]
__device__ float g_h  [NBC * CC * Dd];    // [bc][s][i]
__device__ float g_snap[(size_t)NBC * Dd * Dd];

__device__ __forceinline__ float sigf(float x) { return 1.f / (1.f + __expf(-x)); }
__device__ __forceinline__ float warp_sum(float x) {
#pragma unroll
    for (int o = 16; o >= 1; o >>= 1) x += __shfl_xor_sync(0xffffffffu, x, o);
    return x;
}

template <bool SIG>
__global__ void __launch_bounds__(256) gemm_kernel(const float* __restrict__ A, int lda,
                                                   const float* __restrict__ W,
                                                   float* __restrict__ C, int ldc) {
    __shared__ float As[64][17];
    __shared__ float Ws[64][17];
    int bx = blockIdx.x, by = blockIdx.y, tid = threadIdx.x;
    int tx = tid & 15, ty = tid >> 4;
    int lr = tid >> 2, lk0 = (tid & 3) * 4;
    float acc[4][4];
#pragma unroll
    for (int m = 0; m < 4; m++)
#pragma unroll
        for (int n = 0; n < 4; n++) acc[m][n] = 0.f;
    const float* Arow = A + (size_t)(by * 64 + lr) * lda;
    const float* Wrow = W + (size_t)(bx * 64 + lr) * 128;
#pragma unroll 1
    for (int kt = 0; kt < 8; kt++) {
        int k0 = kt * 16;
        float4 av = *reinterpret_cast<const float4*>(Arow + k0 + lk0);
        float4 wv = *reinterpret_cast<const float4*>(Wrow + k0 + lk0);
        As[lr][lk0 + 0] = av.x; As[lr][lk0 + 1] = av.y;
        As[lr][lk0 + 2] = av.z; As[lr][lk0 + 3] = av.w;
        Ws[lr][lk0 + 0] = wv.x; Ws[lr][lk0 + 1] = wv.y;
        Ws[lr][lk0 + 2] = wv.z; Ws[lr][lk0 + 3] = wv.w;
        __syncthreads();
#pragma unroll
        for (int kk = 0; kk < 16; kk++) {
            float a[4], w[4];
#pragma unroll
            for (int m = 0; m < 4; m++) a[m] = As[ty + 16 * m][kk];
#pragma unroll
            for (int n = 0; n < 4; n++) w[n] = Ws[tx + 16 * n][kk];
#pragma unroll
            for (int m = 0; m < 4; m++)
#pragma unroll
                for (int n = 0; n < 4; n++) acc[m][n] = fmaf(a[m], w[n], acc[m][n]);
        }
        __syncthreads();
    }
#pragma unroll
    for (int m = 0; m < 4; m++) {
        int row = by * 64 + ty + 16 * m;
#pragma unroll
        for (int n = 0; n < 4; n++) {
            float v = acc[m][n];
            if (SIG) v = sigf(v);
            C[(size_t)row * ldc + bx * 64 + tx + 16 * n] = v;
        }
    }
}

__global__ void __launch_bounds__(128) convpack_kernel(const float* __restrict__ qw,
                                                       const float* __restrict__ qb,
                                                       const float* __restrict__ kw,
                                                       const float* __restrict__ kb) {
    int n = blockIdx.x;
    int l = n & (Lseq - 1);
    int d = threadIdx.x;
    int lane = d & 31, w = d >> 5;
    __shared__ float redq[4], redk[4];
    const float* row = g_qkv + (size_t)n * 512;
    float qm = (l > 0)        ? row[-512 + d] : 0.f;
    float qc = row[d];
    float qp = (l < Lseq - 1) ? row[512 + d] : 0.f;
    float yq = fmaf(qw[d * 3 + 0], qm, fmaf(qw[d * 3 + 1], qc, fmaf(qw[d * 3 + 2], qp, qb[d])));
    float sq = sigf(yq);
    float km = (l > 0)        ? row[-512 + 128 + d] : 0.f;
    float kc = row[128 + d];
    float kp = (l < Lseq - 1) ? row[512 + 128 + d] : 0.f;
    float yk = fmaf(kw[d * 3 + 0], km, fmaf(kw[d * 3 + 1], kc, fmaf(kw[d * 3 + 2], kp, kb[d])));
    float sk = sigf(yk);
    float ssq = warp_sum(sq * sq);
    float ssk = warp_sum(sk * sk);
    if (lane == 0) { redq[w] = ssq; redk[w] = ssk; }
    __syncthreads();
    float nq = sqrtf(redq[0] + redq[1] + redq[2] + redq[3]);
    float nk = sqrtf(redk[0] + redk[1] + redk[2] + redk[3]);
    float* out = g_pk + (size_t)n * 640;
    out[d]       = sq / fmaxf(nq, 1e-12f);
    out[128 + d] = sk / fmaxf(nk, 1e-12f);
    out[256 + d] = row[256 + d];
    out[384 + d] = g_g[(size_t)n * 256 + d];
    out[512 + d] = g_g[(size_t)n * 256 + 128 + d];
}

// per-chunk whitened quantities + Phi/Psi/Theta. grid=NBC, 256 thr.
__global__ void __launch_bounds__(256) prep_kernel() {
    int bc = blockIdx.x;
    int b = bc >> 7, c = bc & (NCH - 1);
    int tid = threadIdx.x;
    __shared__ float sK[CC][132], sM1[CC][132], sM2[CC][132];
    __shared__ float sPsi[CC][CC + 1], sTh[CC][CC + 1];
    const float* base = g_pk + ((size_t)b * Lseq + c * CC) * 640;
    if (tid < 128) {
        int j = tid;
        float lam = 1.f;
        float* kapb = g_kap + (size_t)bc * (CC * Dd);
        float* m1b  = g_m1  + (size_t)bc * (CC * Dd);
        float* m2b  = g_m2  + (size_t)bc * (CC * Dd);
        float* lmb  = g_lm  + (size_t)bc * (CC * Dd);
#pragma unroll
        for (int t = 0; t < CC; t++) {
            float k = base[t * 640 + 128 + j];
            float a = base[t * 640 + 384 + j];
            float be = base[t * 640 + 512 + j];
            float kap = lam * k;
            float lamp = lam;
            lam *= a;
            float m = be * k;
            float m1 = __fdividef(m, lam);
            float m2 = __fdividef(m, lamp);
            kapb[t * Dd + j] = kap; m1b[t * Dd + j] = m1;
            m2b [t * Dd + j] = m2;  lmb[t * Dd + j] = lam;
            sK[t][j] = kap; sM1[t][j] = m1; sM2[t][j] = m2;
        }
    }
    __syncthreads();
    int s = tid >> 4, t = tid & 15;
    float phi = 0.f, psi = 0.f;
    if (s < t) {
#pragma unroll
        for (int j4 = 0; j4 < 32; j4++) {
            float4 kk = *reinterpret_cast<float4*>(&sK [t][j4 * 4]);
            float4 m1 = *reinterpret_cast<float4*>(&sM1[s][j4 * 4]);
            float4 m2 = *reinterpret_cast<float4*>(&sM2[s][j4 * 4]);
            phi = fmaf(m1.x, kk.x, fmaf(m1.y, kk.y, fmaf(m1.z, kk.z, fmaf(m1.w, kk.w, phi))));
            psi = fmaf(m2.x, kk.x, fmaf(m2.y, kk.y, fmaf(m2.z, kk.z, fmaf(m2.w, kk.w, psi))));
        }
    }
    sPsi[s][t] = psi;
    g_pt[(size_t)bc * 512 + tid] = phi;
    __syncthreads();
    if (tid < CC) {            // thread = column t of Theta = (I+Psi)^-1
        int tc = tid;
        for (int r = CC - 1; r >= 0; r--) {
            float v;
            if (r > tc) v = 0.f;
            else if (r == tc) v = 1.f;
            else {
                v = 0.f;
                for (int u = r + 1; u <= tc; u++) v -= sPsi[r][u] * sTh[u][tc];
            }
            sTh[r][tc] = v;
        }
    }
    __syncthreads();
    g_pt[(size_t)bc * 512 + 256 + tid] = sTh[s][t];
}

// serial chunk sweep. 128 CTAs (b x 16 groups of 8 rows), 256 thr; warp=row.
__global__ void __launch_bounds__(256, 1) seq_kernel(const float* __restrict__ state,
                                                     float* __restrict__ sfin) {
    int b = blockIdx.x >> 4, g = blockIdx.x & 15;
    int tid = threadIdx.x, w = tid >> 5, lane = tid & 31;
    int i = g * 8 + w, j0 = lane * 4, l16 = lane & 15;
    __shared__ float sK[CC][132], sM1[CC][132], sM2[CC][132];
    __shared__ float sPhi[256], sTh[256], sLC[128];

    float4 s = *reinterpret_cast<const float4*>(state + ((size_t)b * Dd + i) * Dd + j0);

#pragma unroll 1
    for (int c = 0; c < NCH; c++) {
        size_t bc = (size_t)b * NCH + c;
        const float* kapb = g_kap + bc * (CC * Dd);
        const float* m1b  = g_m1  + bc * (CC * Dd);
        const float* m2b  = g_m2  + bc * (CC * Dd);
        for (int f = tid; f < 512; f += 256) {
            int t = f >> 5, jj = (f & 31) * 4;
            *reinterpret_cast<float4*>(&sK [t][jj]) = *reinterpret_cast<const float4*>(kapb + t * Dd + jj);
            *reinterpret_cast<float4*>(&sM1[t][jj]) = *reinterpret_cast<const float4*>(m1b + t * Dd + jj);
            *reinterpret_cast<float4*>(&sM2[t][jj]) = *reinterpret_cast<const float4*>(m2b + t * Dd + jj);
        }
        sPhi[tid] = g_pt[bc * 512 + tid];
        sTh[tid]  = g_pt[bc * 512 + 256 + tid];
        if (tid < 128) sLC[tid] = g_lm[bc * (CC * Dd) + 15 * Dd + tid];
        float vreg = g_pk[((size_t)b * Lseq + c * CC + l16) * 640 + 256 + i];
        __syncthreads();

        // snapshot S_0
        *reinterpret_cast<float4*>(g_snap + bc * (Dd * Dd) + (size_t)i * Dd + j0) = s;

        // P_t = S_row . kappa_t (16 independent allreduces); keep t = l16
        float myP = 0.f;
#pragma unroll
        for (int t = 0; t < CC; t++) {
            float4 kk = *reinterpret_cast<float4*>(&sK[t][j0]);
            float pr = s.x * kk.x;
            pr = fmaf(s.y, kk.y, pr);
            pr = fmaf(s.z, kk.z, pr);
            pr = fmaf(s.w, kk.w, pr);
            pr = warp_sum(pr);
            if (t == l16) myP = pr;
        }
        // rhs_t = P_t + sum_{s<t} Phi[s][t]*v_s   (lane t = l16)
        float rhs = myP;
#pragma unroll
        for (int s2 = 0; s2 < CC; s2++) {
            float vs = __shfl_sync(0xffffffffu, vreg, s2);
            if (s2 < l16) rhs = fmaf(sPhi[s2 * 16 + l16], vs, rhs);
        }
        // h_t = sum_r rhs_r * Theta[r][t]
        float h = 0.f;
#pragma unroll
        for (int r = 0; r < CC; r++) {
            float rr = __shfl_sync(0xffffffffu, rhs, r);
            h = fmaf(rr, sTh[r * 16 + l16], h);
        }
        if (lane < 16) g_h[bc * (CC * Dd) + (size_t)l16 * Dd + i] = h;

        // S = LamC * (S + sum_s (v_s M1_s - h_s M2_s))
        float4 d = make_float4(0.f, 0.f, 0.f, 0.f);
#pragma unroll
        for (int s2 = 0; s2 < CC; s2++) {
            float vs = __shfl_sync(0xffffffffu, vreg, s2);
            float hs = __shfl_sync(0xffffffffu, h, s2);
            float4 m1 = *reinterpret_cast<float4*>(&sM1[s2][j0]);
            float4 m2 = *reinterpret_cast<float4*>(&sM2[s2][j0]);
            d.x = fmaf(vs, m1.x, fmaf(-hs, m2.x, d.x));
            d.y = fmaf(vs, m1.y, fmaf(-hs, m2.y, d.y));
            d.z = fmaf(vs, m1.z, fmaf(-hs, m2.z, d.z));
            d.w = fmaf(vs, m1.w, fmaf(-hs, m2.w, d.w));
        }
        float4 lc = *reinterpret_cast<float4*>(&sLC[j0]);
        s.x = lc.x * (s.x + d.x);
        s.y = lc.y * (s.y + d.y);
        s.z = lc.z * (s.z + d.z);
        s.w = lc.w * (s.w + d.w);
        __syncthreads();
    }

    if (sfin)
        *reinterpret_cast<float4*>(sfin + ((size_t)b * Dd + i) * Dd + j0) = s;
}

// fully parallel per-chunk outputs. grid=NBC, 256 thr, dyn smem.
__global__ void __launch_bounds__(256) outchunk_kernel() {
    extern __shared__ float sm[];
    float* S0  = sm;                   // [128][132]
    float* sQ  = S0 + 128 * 132;       // [16][132] each
    float* sV  = sQ + 16 * 132;
    float* sH  = sV + 16 * 132;
    float* sM1 = sH + 16 * 132;
    float* sM2 = sM1 + 16 * 132;
    float* sZ  = sM2 + 16 * 132;       // Zv[256] | Zh[256]

    int bc = blockIdx.x;
    int b = bc >> 7, c = bc & (NCH - 1);
    int tid = threadIdx.x;

    const float* snap = g_snap + (size_t)bc * (Dd * Dd);
    for (int f = tid; f < 4096; f += 256) {
        int r = f >> 5, jj = (f & 31) * 4;
        *reinterpret_cast<float4*>(&S0[r * 132 + jj]) = *reinterpret_cast<const float4*>(snap + r * Dd + jj);
    }
    const float* pkb = g_pk + ((size_t)b * Lseq + c * CC) * 640;
    const float* hb  = g_h  + (size_t)bc * (CC * Dd);
    const float* m1b = g_m1 + (size_t)bc * (CC * Dd);
    const float* m2b = g_m2 + (size_t)bc * (CC * Dd);
    for (int f = tid; f < 512; f += 256) {
        int t = f >> 5, jj = (f & 31) * 4;
        *reinterpret_cast<float4*>(&sQ [t * 132 + jj]) = *reinterpret_cast<const float4*>(pkb + (size_t)t * 640 + jj);
        *reinterpret_cast<float4*>(&sV [t * 132 + jj]) = *reinterpret_cast<const float4*>(pkb + (size_t)t * 640 + 256 + jj);
        *reinterpret_cast<float4*>(&sH [t * 132 + jj]) = *reinterpret_cast<const float4*>(hb + t * Dd + jj);
        *reinterpret_cast<float4*>(&sM1[t * 132 + jj]) = *reinterpret_cast<const float4*>(m1b + t * Dd + jj);
        *reinterpret_cast<float4*>(&sM2[t * 132 + jj]) = *reinterpret_cast<const float4*>(m2b + t * Dd + jj);
    }
    __syncthreads();

    {   // Zv[t][s] = q_t . v_s ; Zh[t][s] = q_t . h_s
        int t = tid >> 4, s2 = tid & 15;
        float zv = 0.f, zh = 0.f;
#pragma unroll
        for (int j4 = 0; j4 < 32; j4++) {
            float4 q  = *reinterpret_cast<float4*>(&sQ[t * 132 + j4 * 4]);
            float4 vv = *reinterpret_cast<float4*>(&sV[s2 * 132 + j4 * 4]);
            float4 hh = *reinterpret_cast<float4*>(&sH[s2 * 132 + j4 * 4]);
            zv = fmaf(q.x, vv.x, fmaf(q.y, vv.y, fmaf(q.z, vv.z, fmaf(q.w, vv.w, zv))));
            zh = fmaf(q.x, hh.x, fmaf(q.y, hh.y, fmaf(q.z, hh.z, fmaf(q.w, hh.w, zh))));
        }
        sZ[tid] = zv;
        sZ[256 + tid] = zh;
    }
    __syncthreads();

    int t = tid >> 4, jb = (tid & 15) * 8;
    float acc[8];
#pragma unroll
    for (int r = 0; r < 8; r++) acc[r] = 0.f;
    // G_t[j] = sum_i q_t[i] * S0[i][j]
#pragma unroll 4
    for (int i2 = 0; i2 < 128; i2++) {
        float q = sQ[t * 132 + i2];
        float4 a0 = *reinterpret_cast<float4*>(&S0[i2 * 132 + jb]);
        float4 a1 = *reinterpret_cast<float4*>(&S0[i2 * 132 + jb + 4]);
        acc[0] = fmaf(q, a0.x, acc[0]); acc[1] = fmaf(q, a0.y, acc[1]);
        acc[2] = fmaf(q, a0.z, acc[2]); acc[3] = fmaf(q, a0.w, acc[3]);
        acc[4] = fmaf(q, a1.x, acc[4]); acc[5] = fmaf(q, a1.y, acc[5]);
        acc[6] = fmaf(q, a1.z, acc[6]); acc[7] = fmaf(q, a1.w, acc[7]);
    }
    // + sum_{s<=t} Zv[t][s]*M1_s[j] - Zh[t][s]*M2_s[j]
#pragma unroll
    for (int s2 = 0; s2 < CC; s2++) {
        if (s2 <= t) {
            float zv = sZ[t * 16 + s2];
            float zh = sZ[256 + t * 16 + s2];
            float4 m10 = *reinterpret_cast<float4*>(&sM1[s2 * 132 + jb]);
            float4 m11 = *reinterpret_cast<float4*>(&sM1[s2 * 132 + jb + 4]);
            float4 m20 = *reinterpret_cast<float4*>(&sM2[s2 * 132 + jb]);
            float4 m21 = *reinterpret_cast<float4*>(&sM2[s2 * 132 + jb + 4]);
            acc[0] = fmaf(zv, m10.x, fmaf(-zh, m20.x, acc[0]));
            acc[1] = fmaf(zv, m10.y, fmaf(-zh, m20.y, acc[1]));
            acc[2] = fmaf(zv, m10.z, fmaf(-zh, m20.z, acc[2]));
            acc[3] = fmaf(zv, m10.w, fmaf(-zh, m20.w, acc[3]));
            acc[4] = fmaf(zv, m11.x, fmaf(-zh, m21.x, acc[4]));
            acc[5] = fmaf(zv, m11.y, fmaf(-zh, m21.y, acc[5]));
            acc[6] = fmaf(zv, m11.z, fmaf(-zh, m21.z, acc[6]));
            acc[7] = fmaf(zv, m11.w, fmaf(-zh, m21.w, acc[7]));
        }
    }
    const float* lmb = g_lm + (size_t)bc * (CC * Dd) + (size_t)t * Dd + jb;
    float* outp = g_out + ((size_t)b * Lseq + c * CC + t) * Dd + jb;
#pragma unroll
    for (int r = 0; r < 8; r++) {
        float o = lmb[r] * acc[r];
        outp[r] = o * sigf(o);
    }
}

__global__ void __launch_bounds__(128) rms_kernel(const float* __restrict__ rmsw,
                                                  float* __restrict__ out) {
    int n = blockIdx.x;
    int d = threadIdx.x;
    int lane = d & 31, w = d >> 5;
    __shared__ float red[4];
    float v = g_ol[(size_t)n * Dd + d];
    float ss = warp_sum(v * v);
    if (lane == 0) red[w] = ss;
    __syncthreads();
    float mean = (red[0] + red[1] + red[2] + red[3]) * (1.f / 128.f);
    float s = rsqrtf(mean + 1e-6f);
    out[(size_t)n * Dd + d] = v * s * rmsw[d] + g_res[(size_t)n * Dd + d];
}

extern "C" void kernel_launch(void* const* d_in, const int* in_sizes, int n_in,
                              void* d_out, int out_size) {
    const float* x      = (const float*)d_in[0];
    const float* state  = (const float*)d_in[1];
    const float* W_in   = (const float*)d_in[2];
    const float* W_gate = (const float*)d_in[3];
    const float* W_out  = (const float*)d_in[4];
    const float* W_res  = (const float*)d_in[5];
    const float* qconvw = (const float*)d_in[6];
    const float* qconvb = (const float*)d_in[7];
    const float* kconvw = (const float*)d_in[8];
    const float* kconvb = (const float*)d_in[9];
    const float* rmsw   = (const float*)d_in[10];
    float* out = (float*)d_out;

    float *qkv, *gg, *res, *outs, *ol;
    cudaGetSymbolAddress((void**)&qkv,  g_qkv);
    cudaGetSymbolAddress((void**)&gg,   g_g);
    cudaGetSymbolAddress((void**)&res,  g_res);
    cudaGetSymbolAddress((void**)&outs, g_out);
    cudaGetSymbolAddress((void**)&ol,   g_ol);

    float* sfin = (out_size >= BLD + BDD) ? (out + BLD) : nullptr;

    const int oc_smem = (128 * 132 + 5 * 16 * 132 + 512) * 4;
    cudaFuncSetAttribute(outchunk_kernel, cudaFuncAttributeMaxDynamicSharedMemorySize,
                         oc_smem);

    gemm_kernel<false><<<dim3(512 / 64, NROWS / 64), 256>>>(x, Dd, W_in, qkv, 512);
    gemm_kernel<true><<<dim3(256 / 64, NROWS / 64), 256>>>(qkv + 384, 512, W_gate, gg, 256);
    convpack_kernel<<<NROWS, 128>>>(qconvw, qconvb, kconvw, kconvb);
    prep_kernel<<<NBC, 256>>>();
    seq_kernel<<<Bsz * 16, 256>>>(state, sfin);
    gemm_kernel<false><<<dim3(Dd / 64, NROWS / 64), 256>>>(x, Dd, W_res, res, Dd);
    outchunk_kernel<<<NBC, 256, oc_smem>>>();
    gemm_kernel<false><<<dim3(Dd / 64, NROWS / 64), 256>>>(outs, Dd, W_out, ol, Dd);
    rms_kernel<<<NROWS, 128>>>(rmsw, out);
}

// round 15
// speedup vs baseline: 1.1806x; 1.1806x over previous
#include <cuda_runtime.h>
#include <cuda_bf16.h>
#include <cstdint>
#include <math.h>

#define Bsz 8
#define Lseq 2048
#define Dd 128
#define NROWS (Bsz * Lseq)
#define BLD (NROWS * Dd)
#define BDD (Bsz * Dd * Dd)
#define CC 16
#define NCH (Lseq / CC)            // 128
#define NBC (Bsz * NCH)            // 1024

__device__ float g_qkv[NROWS * 512];
__device__ float g_g  [NROWS * 256];
__device__ float g_pk [NROWS * 640];
__device__ float g_res[NROWS * Dd];
__device__ float g_out[NROWS * Dd];
__device__ float g_ol [NROWS * Dd];
__device__ float g_kap[NBC * CC * Dd];
__device__ float g_m1 [NBC * CC * Dd];
__device__ float g_m2 [NBC * CC * Dd];
__device__ float g_lm [NBC * CC * Dd];
__device__ float g_pt [NBC * 512];        // phi[256] | theta[256]
__device__ float g_h  [NBC * CC * Dd];    // [bc][s][i]
__device__ float g_snap[(size_t)NBC * Dd * Dd];

__device__ __forceinline__ float sigf(float x) { return 1.f / (1.f + __expf(-x)); }
__device__ __forceinline__ float warp_sum(float x) {
#pragma unroll
    for (int o = 16; o >= 1; o >>= 1) x += __shfl_xor_sync(0xffffffffu, x, o);
    return x;
}
__device__ __forceinline__ void cp16(float* dst_smem, const float* src) {
    unsigned d = (unsigned)__cvta_generic_to_shared(dst_smem);
    asm volatile("cp.async.cg.shared.global [%0], [%1], 16;" :: "r"(d), "l"(src));
}

template <bool SIG>
__global__ void __launch_bounds__(256) gemm_kernel(const float* __restrict__ A, int lda,
                                                   const float* __restrict__ W,
                                                   float* __restrict__ C, int ldc) {
    __shared__ float As[64][17];
    __shared__ float Ws[64][17];
    int bx = blockIdx.x, by = blockIdx.y, tid = threadIdx.x;
    int tx = tid & 15, ty = tid >> 4;
    int lr = tid >> 2, lk0 = (tid & 3) * 4;
    float acc[4][4];
#pragma unroll
    for (int m = 0; m < 4; m++)
#pragma unroll
        for (int n = 0; n < 4; n++) acc[m][n] = 0.f;
    const float* Arow = A + (size_t)(by * 64 + lr) * lda;
    const float* Wrow = W + (size_t)(bx * 64 + lr) * 128;
#pragma unroll 1
    for (int kt = 0; kt < 8; kt++) {
        int k0 = kt * 16;
        float4 av = *reinterpret_cast<const float4*>(Arow + k0 + lk0);
        float4 wv = *reinterpret_cast<const float4*>(Wrow + k0 + lk0);
        As[lr][lk0 + 0] = av.x; As[lr][lk0 + 1] = av.y;
        As[lr][lk0 + 2] = av.z; As[lr][lk0 + 3] = av.w;
        Ws[lr][lk0 + 0] = wv.x; Ws[lr][lk0 + 1] = wv.y;
        Ws[lr][lk0 + 2] = wv.z; Ws[lr][lk0 + 3] = wv.w;
        __syncthreads();
#pragma unroll
        for (int kk = 0; kk < 16; kk++) {
            float a[4], w[4];
#pragma unroll
            for (int m = 0; m < 4; m++) a[m] = As[ty + 16 * m][kk];
#pragma unroll
            for (int n = 0; n < 4; n++) w[n] = Ws[tx + 16 * n][kk];
#pragma unroll
            for (int m = 0; m < 4; m++)
#pragma unroll
                for (int n = 0; n < 4; n++) acc[m][n] = fmaf(a[m], w[n], acc[m][n]);
        }
        __syncthreads();
    }
#pragma unroll
    for (int m = 0; m < 4; m++) {
        int row = by * 64 + ty + 16 * m;
#pragma unroll
        for (int n = 0; n < 4; n++) {
            float v = acc[m][n];
            if (SIG) v = sigf(v);
            C[(size_t)row * ldc + bx * 64 + tx + 16 * n] = v;
        }
    }
}

__global__ void __launch_bounds__(128) convpack_kernel(const float* __restrict__ qw,
                                                       const float* __restrict__ qb,
                                                       const float* __restrict__ kw,
                                                       const float* __restrict__ kb) {
    int n = blockIdx.x;
    int l = n & (Lseq - 1);
    int d = threadIdx.x;
    int lane = d & 31, w = d >> 5;
    __shared__ float redq[4], redk[4];
    const float* row = g_qkv + (size_t)n * 512;
    float qm = (l > 0)        ? row[-512 + d] : 0.f;
    float qc = row[d];
    float qp = (l < Lseq - 1) ? row[512 + d] : 0.f;
    float yq = fmaf(qw[d * 3 + 0], qm, fmaf(qw[d * 3 + 1], qc, fmaf(qw[d * 3 + 2], qp, qb[d])));
    float sq = sigf(yq);
    float km = (l > 0)        ? row[-512 + 128 + d] : 0.f;
    float kc = row[128 + d];
    float kp = (l < Lseq - 1) ? row[512 + 128 + d] : 0.f;
    float yk = fmaf(kw[d * 3 + 0], km, fmaf(kw[d * 3 + 1], kc, fmaf(kw[d * 3 + 2], kp, kb[d])));
    float sk = sigf(yk);
    float ssq = warp_sum(sq * sq);
    float ssk = warp_sum(sk * sk);
    if (lane == 0) { redq[w] = ssq; redk[w] = ssk; }
    __syncthreads();
    float nq = sqrtf(redq[0] + redq[1] + redq[2] + redq[3]);
    float nk = sqrtf(redk[0] + redk[1] + redk[2] + redk[3]);
    float* out = g_pk + (size_t)n * 640;
    out[d]       = sq / fmaxf(nq, 1e-12f);
    out[128 + d] = sk / fmaxf(nk, 1e-12f);
    out[256 + d] = row[256 + d];
    out[384 + d] = g_g[(size_t)n * 256 + d];
    out[512 + d] = g_g[(size_t)n * 256 + 128 + d];
}

// per-chunk whitened quantities + Phi/Psi/Theta. grid=NBC, 256 thr.
__global__ void __launch_bounds__(256) prep_kernel() {
    int bc = blockIdx.x;
    int b = bc >> 7, c = bc & (NCH - 1);
    int tid = threadIdx.x;
    __shared__ float sK[CC][132], sM1[CC][132], sM2[CC][132];
    __shared__ float sPsi[CC][CC + 1], sTh[CC][CC + 1];
    const float* base = g_pk + ((size_t)b * Lseq + c * CC) * 640;
    if (tid < 128) {
        int j = tid;
        float lam = 1.f;
        float* kapb = g_kap + (size_t)bc * (CC * Dd);
        float* m1b  = g_m1  + (size_t)bc * (CC * Dd);
        float* m2b  = g_m2  + (size_t)bc * (CC * Dd);
        float* lmb  = g_lm  + (size_t)bc * (CC * Dd);
#pragma unroll
        for (int t = 0; t < CC; t++) {
            float k = base[t * 640 + 128 + j];
            float a = base[t * 640 + 384 + j];
            float be = base[t * 640 + 512 + j];
            float kap = lam * k;
            float lamp = lam;
            lam *= a;
            float m = be * k;
            float m1 = __fdividef(m, lam);
            float m2 = __fdividef(m, lamp);
            kapb[t * Dd + j] = kap; m1b[t * Dd + j] = m1;
            m2b [t * Dd + j] = m2;  lmb[t * Dd + j] = lam;
            sK[t][j] = kap; sM1[t][j] = m1; sM2[t][j] = m2;
        }
    }
    __syncthreads();
    int s = tid >> 4, t = tid & 15;
    float phi = 0.f, psi = 0.f;
    if (s < t) {
#pragma unroll
        for (int j4 = 0; j4 < 32; j4++) {
            float4 kk = *reinterpret_cast<float4*>(&sK [t][j4 * 4]);
            float4 m1 = *reinterpret_cast<float4*>(&sM1[s][j4 * 4]);
            float4 m2 = *reinterpret_cast<float4*>(&sM2[s][j4 * 4]);
            phi = fmaf(m1.x, kk.x, fmaf(m1.y, kk.y, fmaf(m1.z, kk.z, fmaf(m1.w, kk.w, phi))));
            psi = fmaf(m2.x, kk.x, fmaf(m2.y, kk.y, fmaf(m2.z, kk.z, fmaf(m2.w, kk.w, psi))));
        }
    }
    sPsi[s][t] = psi;
    g_pt[(size_t)bc * 512 + tid] = phi;
    __syncthreads();
    if (tid < CC) {            // thread = column t of Theta = (I+Psi)^-1
        int tc = tid;
        for (int r = CC - 1; r >= 0; r--) {
            float v;
            if (r > tc) v = 0.f;
            else if (r == tc) v = 1.f;
            else {
                v = 0.f;
                for (int u = r + 1; u <= tc; u++) v -= sPsi[r][u] * sTh[u][tc];
            }
            sTh[r][tc] = v;
        }
    }
    __syncthreads();
    g_pt[(size_t)bc * 512 + 256 + tid] = sTh[s][t];
}

// serial chunk sweep with cp.async double-buffered staging.
// smem layout per buffer: K[2048] M1[2048] M2[2048] PT[512] LC[128] = 6784 floats
#define SEQBUF 6784
__global__ void __launch_bounds__(256, 1) seq_kernel(const float* __restrict__ state,
                                                     float* __restrict__ sfin) {
    extern __shared__ float sb[];
    int b = blockIdx.x >> 4, g = blockIdx.x & 15;
    int tid = threadIdx.x, w = tid >> 5, lane = tid & 31;
    int i = g * 8 + w, j0 = lane * 4, l16 = lane & 15;

    float4 s = *reinterpret_cast<const float4*>(state + ((size_t)b * Dd + i) * Dd + j0);

    // issue staging for chunk 0
    {
        size_t bc0 = (size_t)b * NCH;
        float* dst = sb;
        const float* kapb = g_kap + bc0 * (CC * Dd);
        const float* m1b  = g_m1  + bc0 * (CC * Dd);
        const float* m2b  = g_m2  + bc0 * (CC * Dd);
        for (int f = tid; f < 512; f += 256) {
            cp16(dst + f * 4,        kapb + f * 4);
            cp16(dst + 2048 + f * 4, m1b  + f * 4);
            cp16(dst + 4096 + f * 4, m2b  + f * 4);
        }
        for (int f = tid; f < 128; f += 256)
            cp16(dst + 6144 + f * 4, g_pt + bc0 * 512 + f * 4);
        for (int f = tid; f < 32; f += 256)
            cp16(dst + 6656 + f * 4, g_lm + bc0 * (CC * Dd) + 15 * Dd + f * 4);
        asm volatile("cp.async.commit_group;");
    }
    float vreg = g_pk[((size_t)b * Lseq + l16) * 640 + 256 + i];

#pragma unroll 1
    for (int c = 0; c < NCH; c++) {
        size_t bc = (size_t)b * NCH + c;
        float* buf = sb + (c & 1) * SEQBUF;

        asm volatile("cp.async.wait_group 0;");
        __syncthreads();

        // issue staging for chunk c+1 into other buffer
        if (c + 1 < NCH) {
            size_t bn = bc + 1;
            float* dst = sb + ((c + 1) & 1) * SEQBUF;
            const float* kapb = g_kap + bn * (CC * Dd);
            const float* m1b  = g_m1  + bn * (CC * Dd);
            const float* m2b  = g_m2  + bn * (CC * Dd);
            for (int f = tid; f < 512; f += 256) {
                cp16(dst + f * 4,        kapb + f * 4);
                cp16(dst + 2048 + f * 4, m1b  + f * 4);
                cp16(dst + 4096 + f * 4, m2b  + f * 4);
            }
            for (int f = tid; f < 128; f += 256)
                cp16(dst + 6144 + f * 4, g_pt + bn * 512 + f * 4);
            for (int f = tid; f < 32; f += 256)
                cp16(dst + 6656 + f * 4, g_lm + bn * (CC * Dd) + 15 * Dd + f * 4);
            asm volatile("cp.async.commit_group;");
        }

        const float* sK  = buf;
        const float* sM1 = buf + 2048;
        const float* sM2 = buf + 4096;
        const float* sPhi = buf + 6144;
        const float* sTh  = buf + 6144 + 256;
        const float* sLC  = buf + 6656;

        // prefetch v for chunk c+1
        float vnext = 0.f;
        if (c + 1 < NCH)
            vnext = g_pk[((size_t)b * Lseq + (c + 1) * CC + l16) * 640 + 256 + i];

        // snapshot S_0
        *reinterpret_cast<float4*>(g_snap + bc * (Dd * Dd) + (size_t)i * Dd + j0) = s;

        // P_t = S_row . kappa_t; keep t = l16
        float myP = 0.f;
#pragma unroll
        for (int t = 0; t < CC; t++) {
            float4 kk = *reinterpret_cast<const float4*>(sK + t * Dd + j0);
            float pr = s.x * kk.x;
            pr = fmaf(s.y, kk.y, pr);
            pr = fmaf(s.z, kk.z, pr);
            pr = fmaf(s.w, kk.w, pr);
            pr = warp_sum(pr);
            if (t == l16) myP = pr;
        }
        // rhs_t = P_t + sum_{s<t} Phi[s][t]*v_s
        float rhs = myP;
#pragma unroll
        for (int s2 = 0; s2 < CC; s2++) {
            float vs = __shfl_sync(0xffffffffu, vreg, s2);
            if (s2 < l16) rhs = fmaf(sPhi[s2 * 16 + l16], vs, rhs);
        }
        // h_t = sum_r rhs_r * Theta[r][t]
        float h = 0.f;
#pragma unroll
        for (int r = 0; r < CC; r++) {
            float rr = __shfl_sync(0xffffffffu, rhs, r);
            h = fmaf(rr, sTh[r * 16 + l16], h);
        }
        if (lane < 16) g_h[bc * (CC * Dd) + (size_t)l16 * Dd + i] = h;

        // S = LamC * (S + sum_s (v_s M1_s - h_s M2_s))
        float4 d = make_float4(0.f, 0.f, 0.f, 0.f);
#pragma unroll
        for (int s2 = 0; s2 < CC; s2++) {
            float vs = __shfl_sync(0xffffffffu, vreg, s2);
            float hs = __shfl_sync(0xffffffffu, h, s2);
            float4 m1 = *reinterpret_cast<const float4*>(sM1 + s2 * Dd + j0);
            float4 m2 = *reinterpret_cast<const float4*>(sM2 + s2 * Dd + j0);
            d.x = fmaf(vs, m1.x, fmaf(-hs, m2.x, d.x));
            d.y = fmaf(vs, m1.y, fmaf(-hs, m2.y, d.y));
            d.z = fmaf(vs, m1.z, fmaf(-hs, m2.z, d.z));
            d.w = fmaf(vs, m1.w, fmaf(-hs, m2.w, d.w));
        }
        float4 lc = *reinterpret_cast<const float4*>(sLC + j0);
        s.x = lc.x * (s.x + d.x);
        s.y = lc.y * (s.y + d.y);
        s.z = lc.z * (s.z + d.z);
        s.w = lc.w * (s.w + d.w);
        vreg = vnext;
    }

    if (sfin)
        *reinterpret_cast<float4*>(sfin + ((size_t)b * Dd + i) * Dd + j0) = s;
}

// fully parallel per-chunk outputs. grid=NBC, 256 thr, dyn smem.
__global__ void __launch_bounds__(256) outchunk_kernel() {
    extern __shared__ float sm[];
    float* S0  = sm;                   // [128][132]
    float* sQ  = S0 + 128 * 132;       // [16][132] each
    float* sV  = sQ + 16 * 132;
    float* sH  = sV + 16 * 132;
    float* sM1 = sH + 16 * 132;
    float* sM2 = sM1 + 16 * 132;
    float* sZ  = sM2 + 16 * 132;       // Zv[256] | Zh[256]

    int bc = blockIdx.x;
    int b = bc >> 7, c = bc & (NCH - 1);
    int tid = threadIdx.x;

    const float* snap = g_snap + (size_t)bc * (Dd * Dd);
    for (int f = tid; f < 4096; f += 256) {
        int r = f >> 5, jj = (f & 31) * 4;
        *reinterpret_cast<float4*>(&S0[r * 132 + jj]) = *reinterpret_cast<const float4*>(snap + r * Dd + jj);
    }
    const float* pkb = g_pk + ((size_t)b * Lseq + c * CC) * 640;
    const float* hb  = g_h  + (size_t)bc * (CC * Dd);
    const float* m1b = g_m1 + (size_t)bc * (CC * Dd);
    const float* m2b = g_m2 + (size_t)bc * (CC * Dd);
    for (int f = tid; f < 512; f += 256) {
        int t = f >> 5, jj = (f & 31) * 4;
        *reinterpret_cast<float4*>(&sQ [t * 132 + jj]) = *reinterpret_cast<const float4*>(pkb + (size_t)t * 640 + jj);
        *reinterpret_cast<float4*>(&sV [t * 132 + jj]) = *reinterpret_cast<const float4*>(pkb + (size_t)t * 640 + 256 + jj);
        *reinterpret_cast<float4*>(&sH [t * 132 + jj]) = *reinterpret_cast<const float4*>(hb + t * Dd + jj);
        *reinterpret_cast<float4*>(&sM1[t * 132 + jj]) = *reinterpret_cast<const float4*>(m1b + t * Dd + jj);
        *reinterpret_cast<float4*>(&sM2[t * 132 + jj]) = *reinterpret_cast<const float4*>(m2b + t * Dd + jj);
    }
    __syncthreads();

    {   // Zv[t][s] = q_t . v_s ; Zh[t][s] = q_t . h_s
        int t = tid >> 4, s2 = tid & 15;
        float zv = 0.f, zh = 0.f;
#pragma unroll
        for (int j4 = 0; j4 < 32; j4++) {
            float4 q  = *reinterpret_cast<float4*>(&sQ[t * 132 + j4 * 4]);
            float4 vv = *reinterpret_cast<float4*>(&sV[s2 * 132 + j4 * 4]);
            float4 hh = *reinterpret_cast<float4*>(&sH[s2 * 132 + j4 * 4]);
            zv = fmaf(q.x, vv.x, fmaf(q.y, vv.y, fmaf(q.z, vv.z, fmaf(q.w, vv.w, zv))));
            zh = fmaf(q.x, hh.x, fmaf(q.y, hh.y, fmaf(q.z, hh.z, fmaf(q.w, hh.w, zh))));
        }
        sZ[tid] = zv;
        sZ[256 + tid] = zh;
    }
    __syncthreads();

    int t = tid >> 4, jb = (tid & 15) * 8;
    float acc[8];
#pragma unroll
    for (int r = 0; r < 8; r++) acc[r] = 0.f;
#pragma unroll 4
    for (int i2 = 0; i2 < 128; i2++) {
        float q = sQ[t * 132 + i2];
        float4 a0 = *reinterpret_cast<float4*>(&S0[i2 * 132 + jb]);
        float4 a1 = *reinterpret_cast<float4*>(&S0[i2 * 132 + jb + 4]);
        acc[0] = fmaf(q, a0.x, acc[0]); acc[1] = fmaf(q, a0.y, acc[1]);
        acc[2] = fmaf(q, a0.z, acc[2]); acc[3] = fmaf(q, a0.w, acc[3]);
        acc[4] = fmaf(q, a1.x, acc[4]); acc[5] = fmaf(q, a1.y, acc[5]);
        acc[6] = fmaf(q, a1.z, acc[6]); acc[7] = fmaf(q, a1.w, acc[7]);
    }
#pragma unroll
    for (int s2 = 0; s2 < CC; s2++) {
        if (s2 <= t) {
            float zv = sZ[t * 16 + s2];
            float zh = sZ[256 + t * 16 + s2];
            float4 m10 = *reinterpret_cast<float4*>(&sM1[s2 * 132 + jb]);
            float4 m11 = *reinterpret_cast<float4*>(&sM1[s2 * 132 + jb + 4]);
            float4 m20 = *reinterpret_cast<float4*>(&sM2[s2 * 132 + jb]);
            float4 m21 = *reinterpret_cast<float4*>(&sM2[s2 * 132 + jb + 4]);
            acc[0] = fmaf(zv, m10.x, fmaf(-zh, m20.x, acc[0]));
            acc[1] = fmaf(zv, m10.y, fmaf(-zh, m20.y, acc[1]));
            acc[2] = fmaf(zv, m10.z, fmaf(-zh, m20.z, acc[2]));
            acc[3] = fmaf(zv, m10.w, fmaf(-zh, m20.w, acc[3]));
            acc[4] = fmaf(zv, m11.x, fmaf(-zh, m21.x, acc[4]));
            acc[5] = fmaf(zv, m11.y, fmaf(-zh, m21.y, acc[5]));
            acc[6] = fmaf(zv, m11.z, fmaf(-zh, m21.z, acc[6]));
            acc[7] = fmaf(zv, m11.w, fmaf(-zh, m21.w, acc[7]));
        }
    }
    const float* lmb = g_lm + (size_t)bc * (CC * Dd) + (size_t)t * Dd + jb;
    float* outp = g_out + ((size_t)b * Lseq + c * CC + t) * Dd + jb;
#pragma unroll
    for (int r = 0; r < 8; r++) {
        float o = lmb[r] * acc[r];
        outp[r] = o * sigf(o);
    }
}

__global__ void __launch_bounds__(128) rms_kernel(const float* __restrict__ rmsw,
                                                  float* __restrict__ out) {
    int n = blockIdx.x;
    int d = threadIdx.x;
    int lane = d & 31, w = d >> 5;
    __shared__ float red[4];
    float v = g_ol[(size_t)n * Dd + d];
    float ss = warp_sum(v * v);
    if (lane == 0) red[w] = ss;
    __syncthreads();
    float mean = (red[0] + red[1] + red[2] + red[3]) * (1.f / 128.f);
    float s = rsqrtf(mean + 1e-6f);
    out[(size_t)n * Dd + d] = v * s * rmsw[d] + g_res[(size_t)n * Dd + d];
}

extern "C" void kernel_launch(void* const* d_in, const int* in_sizes, int n_in,
                              void* d_out, int out_size) {
    const float* x      = (const float*)d_in[0];
    const float* state  = (const float*)d_in[1];
    const float* W_in   = (const float*)d_in[2];
    const float* W_gate = (const float*)d_in[3];
    const float* W_out  = (const float*)d_in[4];
    const float* W_res  = (const float*)d_in[5];
    const float* qconvw = (const float*)d_in[6];
    const float* qconvb = (const float*)d_in[7];
    const float* kconvw = (const float*)d_in[8];
    const float* kconvb = (const float*)d_in[9];
    const float* rmsw   = (const float*)d_in[10];
    float* out = (float*)d_out;

    float *qkv, *gg, *res, *outs, *ol;
    cudaGetSymbolAddress((void**)&qkv,  g_qkv);
    cudaGetSymbolAddress((void**)&gg,   g_g);
    cudaGetSymbolAddress((void**)&res,  g_res);
    cudaGetSymbolAddress((void**)&outs, g_out);
    cudaGetSymbolAddress((void**)&ol,   g_ol);

    float* sfin = (out_size >= BLD + BDD) ? (out + BLD) : nullptr;

    const int oc_smem = (128 * 132 + 5 * 16 * 132 + 512) * 4;
    cudaFuncSetAttribute(outchunk_kernel, cudaFuncAttributeMaxDynamicSharedMemorySize,
                         oc_smem);
    const int seq_smem = 2 * SEQBUF * 4;    // 54272 B
    cudaFuncSetAttribute(seq_kernel, cudaFuncAttributeMaxDynamicSharedMemorySize,
                         seq_smem);

    gemm_kernel<false><<<dim3(512 / 64, NROWS / 64), 256>>>(x, Dd, W_in, qkv, 512);
    gemm_kernel<true><<<dim3(256 / 64, NROWS / 64), 256>>>(qkv + 384, 512, W_gate, gg, 256);
    convpack_kernel<<<NROWS, 128>>>(qconvw, qconvb, kconvw, kconvb);
    prep_kernel<<<NBC, 256>>>();
    seq_kernel<<<Bsz * 16, 256, seq_smem>>>(state, sfin);
    gemm_kernel<false><<<dim3(Dd / 64, NROWS / 64), 256>>>(x, Dd, W_res, res, Dd);
    outchunk_kernel<<<NBC, 256, oc_smem>>>();
    gemm_kernel<false><<<dim3(Dd / 64, NROWS / 64), 256>>>(outs, Dd, W_out, ol, Dd);
    rms_kernel<<<NROWS, 128>>>(rmsw, out);
}

// round 17
// speedup vs baseline: 1.2481x; 1.0572x over previous
#include <cuda_runtime.h>
#include <cuda_bf16.h>
#include <cstdint>
#include <math.h>

#define Bsz 8
#define Lseq 2048
#define Dd 128
#define NROWS (Bsz * Lseq)
#define BLD (NROWS * Dd)
#define BDD (Bsz * Dd * Dd)
#define CC 16
#define NCH (Lseq / CC)            // 128
#define NBC (Bsz * NCH)            // 1024

__device__ float g_qkv[NROWS * 512];
__device__ float g_g  [NROWS * 256];
__device__ float g_pk [NROWS * 640];
__device__ float g_res[NROWS * Dd];
__device__ float g_out[NROWS * Dd];
__device__ float g_ol [NROWS * Dd];
__device__ float g_kap[NBC * CC * Dd];
__device__ float g_m1 [NBC * CC * Dd];
__device__ float g_m2 [NBC * CC * Dd];
__device__ float g_lm [NBC * CC * Dd];
__device__ float g_pt [NBC * 512];        // phi[256] | theta[256]
__device__ float g_h  [NBC * CC * Dd];    // [bc][s][i]
__device__ float g_snap[(size_t)NBC * Dd * Dd];

__device__ __forceinline__ float sigf(float x) { return 1.f / (1.f + __expf(-x)); }
__device__ __forceinline__ float warp_sum(float x) {
#pragma unroll
    for (int o = 16; o >= 1; o >>= 1) x += __shfl_xor_sync(0xffffffffu, x, o);
    return x;
}
__device__ __forceinline__ void cp16(float* dst_smem, const float* src) {
    unsigned d = (unsigned)__cvta_generic_to_shared(dst_smem);
    asm volatile("cp.async.cg.shared.global [%0], [%1], 16;" :: "r"(d), "l"(src));
}

template <bool SIG>
__global__ void __launch_bounds__(256) gemm_kernel(const float* __restrict__ A, int lda,
                                                   const float* __restrict__ W,
                                                   float* __restrict__ C, int ldc) {
    __shared__ float As[64][17];
    __shared__ float Ws[64][17];
    int bx = blockIdx.x, by = blockIdx.y, tid = threadIdx.x;
    int tx = tid & 15, ty = tid >> 4;
    int lr = tid >> 2, lk0 = (tid & 3) * 4;
    float acc[4][4];
#pragma unroll
    for (int m = 0; m < 4; m++)
#pragma unroll
        for (int n = 0; n < 4; n++) acc[m][n] = 0.f;
    const float* Arow = A + (size_t)(by * 64 + lr) * lda;
    const float* Wrow = W + (size_t)(bx * 64 + lr) * 128;
#pragma unroll 1
    for (int kt = 0; kt < 8; kt++) {
        int k0 = kt * 16;
        float4 av = *reinterpret_cast<const float4*>(Arow + k0 + lk0);
        float4 wv = *reinterpret_cast<const float4*>(Wrow + k0 + lk0);
        As[lr][lk0 + 0] = av.x; As[lr][lk0 + 1] = av.y;
        As[lr][lk0 + 2] = av.z; As[lr][lk0 + 3] = av.w;
        Ws[lr][lk0 + 0] = wv.x; Ws[lr][lk0 + 1] = wv.y;
        Ws[lr][lk0 + 2] = wv.z; Ws[lr][lk0 + 3] = wv.w;
        __syncthreads();
#pragma unroll
        for (int kk = 0; kk < 16; kk++) {
            float a[4], w[4];
#pragma unroll
            for (int m = 0; m < 4; m++) a[m] = As[ty + 16 * m][kk];
#pragma unroll
            for (int n = 0; n < 4; n++) w[n] = Ws[tx + 16 * n][kk];
#pragma unroll
            for (int m = 0; m < 4; m++)
#pragma unroll
                for (int n = 0; n < 4; n++) acc[m][n] = fmaf(a[m], w[n], acc[m][n]);
        }
        __syncthreads();
    }
#pragma unroll
    for (int m = 0; m < 4; m++) {
        int row = by * 64 + ty + 16 * m;
#pragma unroll
        for (int n = 0; n < 4; n++) {
            float v = acc[m][n];
            if (SIG) v = sigf(v);
            C[(size_t)row * ldc + bx * 64 + tx + 16 * n] = v;
        }
    }
}

// fused: conv+sigmoid+L2norm for 16 rows + whitened chunk quantities + Phi/Psi/Theta
__global__ void __launch_bounds__(256) prep_kernel(const float* __restrict__ qw,
                                                   const float* __restrict__ qb,
                                                   const float* __restrict__ kw,
                                                   const float* __restrict__ kb) {
    int bc = blockIdx.x;
    int b = bc >> 7, c = bc & (NCH - 1);
    int tid = threadIdx.x;
    __shared__ float sK[CC][132], sM1[CC][132], sM2[CC][132];
    __shared__ float sPsi[CC][CC + 1], sTh[CC][CC + 1];
    __shared__ float redq[2][4], redk[2][4];

    int h = tid >> 7;            // which of the 2 rows this pass
    int d = tid & 127;
    int lane = tid & 31, wid = (tid & 127) >> 5;

    // phase 1: conv + sigmoid + L2 norm, 2 rows per pass
#pragma unroll 1
    for (int tp = 0; tp < 8; tp++) {
        int t = tp * 2 + h;
        int n = b * Lseq + c * CC + t;
        int l = c * CC + t;
        const float* row = g_qkv + (size_t)n * 512;
        float qm = (l > 0)        ? row[-512 + d] : 0.f;
        float qc = row[d];
        float qp = (l < Lseq - 1) ? row[512 + d] : 0.f;
        float yq = fmaf(qw[d * 3 + 0], qm, fmaf(qw[d * 3 + 1], qc, fmaf(qw[d * 3 + 2], qp, qb[d])));
        float sq = sigf(yq);
        float km = (l > 0)        ? row[-512 + 128 + d] : 0.f;
        float kc = row[128 + d];
        float kp = (l < Lseq - 1) ? row[512 + 128 + d] : 0.f;
        float yk = fmaf(kw[d * 3 + 0], km, fmaf(kw[d * 3 + 1], kc, fmaf(kw[d * 3 + 2], kp, kb[d])));
        float sk = sigf(yk);
        float ssq = warp_sum(sq * sq);
        float ssk = warp_sum(sk * sk);
        if (lane == 0) { redq[h][wid] = ssq; redk[h][wid] = ssk; }
        __syncthreads();
        float nq = sqrtf(redq[h][0] + redq[h][1] + redq[h][2] + redq[h][3]);
        float nk = sqrtf(redk[h][0] + redk[h][1] + redk[h][2] + redk[h][3]);
        float* out = g_pk + (size_t)n * 640;
        out[d]       = sq / fmaxf(nq, 1e-12f);
        out[256 + d] = row[256 + d];                // v
        sK[t][d] = sk / fmaxf(nk, 1e-12f);          // normalized k (pre-kappa)
        __syncthreads();
    }

    // phase 2: whitened quantities per channel
    if (tid < 128) {
        int j = tid;
        float lam = 1.f;
        float* kapb = g_kap + (size_t)bc * (CC * Dd);
        float* m1b  = g_m1  + (size_t)bc * (CC * Dd);
        float* m2b  = g_m2  + (size_t)bc * (CC * Dd);
        float* lmb  = g_lm  + (size_t)bc * (CC * Dd);
        const float* gb = g_g + ((size_t)(b * Lseq + c * CC)) * 256;
#pragma unroll
        for (int t = 0; t < CC; t++) {
            float k  = sK[t][j];
            float a  = gb[(size_t)t * 256 + j];
            float be = gb[(size_t)t * 256 + 128 + j];
            float kap = lam * k;
            float lamp = lam;
            lam *= a;
            float m = be * k;
            float m1 = __fdividef(m, lam);
            float m2 = __fdividef(m, lamp);
            kapb[t * Dd + j] = kap; m1b[t * Dd + j] = m1;
            m2b [t * Dd + j] = m2;  lmb[t * Dd + j] = lam;
            sK[t][j] = kap; sM1[t][j] = m1; sM2[t][j] = m2;
        }
    }
    __syncthreads();

    int s = tid >> 4, t = tid & 15;
    float phi = 0.f, psi = 0.f;
    if (s < t) {
#pragma unroll
        for (int j4 = 0; j4 < 32; j4++) {
            float4 kk = *reinterpret_cast<float4*>(&sK [t][j4 * 4]);
            float4 m1 = *reinterpret_cast<float4*>(&sM1[s][j4 * 4]);
            float4 m2 = *reinterpret_cast<float4*>(&sM2[s][j4 * 4]);
            phi = fmaf(m1.x, kk.x, fmaf(m1.y, kk.y, fmaf(m1.z, kk.z, fmaf(m1.w, kk.w, phi))));
            psi = fmaf(m2.x, kk.x, fmaf(m2.y, kk.y, fmaf(m2.z, kk.z, fmaf(m2.w, kk.w, psi))));
        }
    }
    sPsi[s][t] = psi;
    g_pt[(size_t)bc * 512 + tid] = phi;
    __syncthreads();
    if (tid < CC) {              // column tc of Theta = (I+Psi)^-1
        int tc = tid;
        for (int r = CC - 1; r >= 0; r--) {
            float v;
            if (r > tc) v = 0.f;
            else if (r == tc) v = 1.f;
            else {
                v = 0.f;
                for (int u = r + 1; u <= tc; u++) v -= sPsi[r][u] * sTh[u][tc];
            }
            sTh[r][tc] = v;
        }
    }
    __syncthreads();
    g_pt[(size_t)bc * 512 + 256 + tid] = sTh[s][t];
}

// serial chunk sweep: cp.async double-buffered staging + transpose-reduced P-dots
#define SEQBUF 6784
__global__ void __launch_bounds__(256, 1) seq_kernel(const float* __restrict__ state,
                                                     float* __restrict__ sfin) {
    extern __shared__ float sb[];
    int b = blockIdx.x >> 4, g = blockIdx.x & 15;
    int tid = threadIdx.x, w = tid >> 5, lane = tid & 31;
    int i = g * 8 + w, j0 = lane * 4, l16 = lane & 15;

    float4 s = *reinterpret_cast<const float4*>(state + ((size_t)b * Dd + i) * Dd + j0);

    {
        size_t bc0 = (size_t)b * NCH;
        float* dst = sb;
        const float* kapb = g_kap + bc0 * (CC * Dd);
        const float* m1b  = g_m1  + bc0 * (CC * Dd);
        const float* m2b  = g_m2  + bc0 * (CC * Dd);
        for (int f = tid; f < 512; f += 256) {
            cp16(dst + f * 4,        kapb + f * 4);
            cp16(dst + 2048 + f * 4, m1b  + f * 4);
            cp16(dst + 4096 + f * 4, m2b  + f * 4);
        }
        for (int f = tid; f < 128; f += 256)
            cp16(dst + 6144 + f * 4, g_pt + bc0 * 512 + f * 4);
        for (int f = tid; f < 32; f += 256)
            cp16(dst + 6656 + f * 4, g_lm + bc0 * (CC * Dd) + 15 * Dd + f * 4);
        asm volatile("cp.async.commit_group;");
    }
    float vreg = g_pk[((size_t)b * Lseq + l16) * 640 + 256 + i];

#pragma unroll 1
    for (int c = 0; c < NCH; c++) {
        size_t bc = (size_t)b * NCH + c;
        float* buf = sb + (c & 1) * SEQBUF;

        asm volatile("cp.async.wait_group 0;");
        __syncthreads();

        if (c + 1 < NCH) {
            size_t bn = bc + 1;
            float* dst = sb + ((c + 1) & 1) * SEQBUF;
            const float* kapb = g_kap + bn * (CC * Dd);
            const float* m1b  = g_m1  + bn * (CC * Dd);
            const float* m2b  = g_m2  + bn * (CC * Dd);
            for (int f = tid; f < 512; f += 256) {
                cp16(dst + f * 4,        kapb + f * 4);
                cp16(dst + 2048 + f * 4, m1b  + f * 4);
                cp16(dst + 4096 + f * 4, m2b  + f * 4);
            }
            for (int f = tid; f < 128; f += 256)
                cp16(dst + 6144 + f * 4, g_pt + bn * 512 + f * 4);
            for (int f = tid; f < 32; f += 256)
                cp16(dst + 6656 + f * 4, g_lm + bn * (CC * Dd) + 15 * Dd + f * 4);
            asm volatile("cp.async.commit_group;");
        }

        const float* sK   = buf;
        const float* sM1  = buf + 2048;
        const float* sM2  = buf + 4096;
        const float* sPhi = buf + 6144;
        const float* sTh  = buf + 6144 + 256;
        const float* sLC  = buf + 6656;

        float vnext = 0.f;
        if (c + 1 < NCH)
            vnext = g_pk[((size_t)b * Lseq + (c + 1) * CC + l16) * 640 + 256 + i];

        *reinterpret_cast<float4*>(g_snap + bc * (Dd * Dd) + (size_t)i * Dd + j0) = s;

        // P_t = S_row . kappa_t : 16 partial dots, transpose-reduced (17 shfl)
        float P[CC];
#pragma unroll
        for (int t = 0; t < CC; t++) {
            float4 kk = *reinterpret_cast<const float4*>(sK + t * Dd + j0);
            float pr = s.x * kk.x;
            pr = fmaf(s.y, kk.y, pr);
            pr = fmaf(s.z, kk.z, pr);
            pr = fmaf(s.w, kk.w, pr);
            P[t] = pr;
        }
        {
            int cnt = CC;
#pragma unroll
            for (int o = 16; o >= 2; o >>= 1) {
                int hf = cnt >> 1;
                bool up = (lane & o) != 0;
#pragma unroll
                for (int m = 0; m < 8; m++) {
                    if (m < hf) {
                        float keep = up ? P[m + hf] : P[m];
                        float give = up ? P[m] : P[m + hf];
                        float recv = __shfl_xor_sync(0xffffffffu, give, o);
                        P[m] = keep + recv;
                    }
                }
                cnt = hf;
            }
            P[0] += __shfl_xor_sync(0xffffffffu, P[0], 1);
        }
        float myP = __shfl_sync(0xffffffffu, P[0], 2 * l16);

        // rhs_t = P_t + sum_{s<t} Phi[s][t]*v_s
        float rhs = myP;
#pragma unroll
        for (int s2 = 0; s2 < CC; s2++) {
            float vs = __shfl_sync(0xffffffffu, vreg, s2);
            if (s2 < l16) rhs = fmaf(sPhi[s2 * 16 + l16], vs, rhs);
        }
        // h_t = sum_r rhs_r * Theta[r][t]
        float h = 0.f;
#pragma unroll
        for (int r = 0; r < CC; r++) {
            float rr = __shfl_sync(0xffffffffu, rhs, r);
            h = fmaf(rr, sTh[r * 16 + l16], h);
        }
        if (lane < 16) g_h[bc * (CC * Dd) + (size_t)l16 * Dd + i] = h;

        // S = LamC * (S + sum_s (v_s M1_s - h_s M2_s))
        float4 d = make_float4(0.f, 0.f, 0.f, 0.f);
#pragma unroll
        for (int s2 = 0; s2 < CC; s2++) {
            float vs = __shfl_sync(0xffffffffu, vreg, s2);
            float hs = __shfl_sync(0xffffffffu, h, s2);
            float4 m1 = *reinterpret_cast<const float4*>(sM1 + s2 * Dd + j0);
            float4 m2 = *reinterpret_cast<const float4*>(sM2 + s2 * Dd + j0);
            d.x = fmaf(vs, m1.x, fmaf(-hs, m2.x, d.x));
            d.y = fmaf(vs, m1.y, fmaf(-hs, m2.y, d.y));
            d.z = fmaf(vs, m1.z, fmaf(-hs, m2.z, d.z));
            d.w = fmaf(vs, m1.w, fmaf(-hs, m2.w, d.w));
        }
        float4 lc = *reinterpret_cast<const float4*>(sLC + j0);
        s.x = lc.x * (s.x + d.x);
        s.y = lc.y * (s.y + d.y);
        s.z = lc.z * (s.z + d.z);
        s.w = lc.w * (s.w + d.w);
        vreg = vnext;
    }

    if (sfin)
        *reinterpret_cast<float4*>(sfin + ((size_t)b * Dd + i) * Dd + j0) = s;
}

// fully parallel per-chunk outputs
__global__ void __launch_bounds__(256) outchunk_kernel() {
    extern __shared__ float sm[];
    float* S0  = sm;
    float* sQ  = S0 + 128 * 132;
    float* sV  = sQ + 16 * 132;
    float* sH  = sV + 16 * 132;
    float* sM1 = sH + 16 * 132;
    float* sM2 = sM1 + 16 * 132;
    float* sZ  = sM2 + 16 * 132;

    int bc = blockIdx.x;
    int b = bc >> 7, c = bc & (NCH - 1);
    int tid = threadIdx.x;

    const float* snap = g_snap + (size_t)bc * (Dd * Dd);
    for (int f = tid; f < 4096; f += 256) {
        int r = f >> 5, jj = (f & 31) * 4;
        *reinterpret_cast<float4*>(&S0[r * 132 + jj]) = *reinterpret_cast<const float4*>(snap + r * Dd + jj);
    }
    const float* pkb = g_pk + ((size_t)b * Lseq + c * CC) * 640;
    const float* hb  = g_h  + (size_t)bc * (CC * Dd);
    const float* m1b = g_m1 + (size_t)bc * (CC * Dd);
    const float* m2b = g_m2 + (size_t)bc * (CC * Dd);
    for (int f = tid; f < 512; f += 256) {
        int t = f >> 5, jj = (f & 31) * 4;
        *reinterpret_cast<float4*>(&sQ [t * 132 + jj]) = *reinterpret_cast<const float4*>(pkb + (size_t)t * 640 + jj);
        *reinterpret_cast<float4*>(&sV [t * 132 + jj]) = *reinterpret_cast<const float4*>(pkb + (size_t)t * 640 + 256 + jj);
        *reinterpret_cast<float4*>(&sH [t * 132 + jj]) = *reinterpret_cast<const float4*>(hb + t * Dd + jj);
        *reinterpret_cast<float4*>(&sM1[t * 132 + jj]) = *reinterpret_cast<const float4*>(m1b + t * Dd + jj);
        *reinterpret_cast<float4*>(&sM2[t * 132 + jj]) = *reinterpret_cast<const float4*>(m2b + t * Dd + jj);
    }
    __syncthreads();

    {
        int t = tid >> 4, s2 = tid & 15;
        float zv = 0.f, zh = 0.f;
#pragma unroll
        for (int j4 = 0; j4 < 32; j4++) {
            float4 q  = *reinterpret_cast<float4*>(&sQ[t * 132 + j4 * 4]);
            float4 vv = *reinterpret_cast<float4*>(&sV[s2 * 132 + j4 * 4]);
            float4 hh = *reinterpret_cast<float4*>(&sH[s2 * 132 + j4 * 4]);
            zv = fmaf(q.x, vv.x, fmaf(q.y, vv.y, fmaf(q.z, vv.z, fmaf(q.w, vv.w, zv))));
            zh = fmaf(q.x, hh.x, fmaf(q.y, hh.y, fmaf(q.z, hh.z, fmaf(q.w, hh.w, zh))));
        }
        sZ[tid] = zv;
        sZ[256 + tid] = zh;
    }
    __syncthreads();

    int t = tid >> 4, jb = (tid & 15) * 8;
    float acc[8];
#pragma unroll
    for (int r = 0; r < 8; r++) acc[r] = 0.f;
#pragma unroll 4
    for (int i2 = 0; i2 < 128; i2++) {
        float q = sQ[t * 132 + i2];
        float4 a0 = *reinterpret_cast<float4*>(&S0[i2 * 132 + jb]);
        float4 a1 = *reinterpret_cast<float4*>(&S0[i2 * 132 + jb + 4]);
        acc[0] = fmaf(q, a0.x, acc[0]); acc[1] = fmaf(q, a0.y, acc[1]);
        acc[2] = fmaf(q, a0.z, acc[2]); acc[3] = fmaf(q, a0.w, acc[3]);
        acc[4] = fmaf(q, a1.x, acc[4]); acc[5] = fmaf(q, a1.y, acc[5]);
        acc[6] = fmaf(q, a1.z, acc[6]); acc[7] = fmaf(q, a1.w, acc[7]);
    }
#pragma unroll
    for (int s2 = 0; s2 < CC; s2++) {
        if (s2 <= t) {
            float zv = sZ[t * 16 + s2];
            float zh = sZ[256 + t * 16 + s2];
            float4 m10 = *reinterpret_cast<float4*>(&sM1[s2 * 132 + jb]);
            float4 m11 = *reinterpret_cast<float4*>(&sM1[s2 * 132 + jb + 4]);
            float4 m20 = *reinterpret_cast<float4*>(&sM2[s2 * 132 + jb]);
            float4 m21 = *reinterpret_cast<float4*>(&sM2[s2 * 132 + jb + 4]);
            acc[0] = fmaf(zv, m10.x, fmaf(-zh, m20.x, acc[0]));
            acc[1] = fmaf(zv, m10.y, fmaf(-zh, m20.y, acc[1]));
            acc[2] = fmaf(zv, m10.z, fmaf(-zh, m20.z, acc[2]));
            acc[3] = fmaf(zv, m10.w, fmaf(-zh, m20.w, acc[3]));
            acc[4] = fmaf(zv, m11.x, fmaf(-zh, m21.x, acc[4]));
            acc[5] = fmaf(zv, m11.y, fmaf(-zh, m21.y, acc[5]));
            acc[6] = fmaf(zv, m11.z, fmaf(-zh, m21.z, acc[6]));
            acc[7] = fmaf(zv, m11.w, fmaf(-zh, m21.w, acc[7]));
        }
    }
    const float* lmb = g_lm + (size_t)bc * (CC * Dd) + (size_t)t * Dd + jb;
    float* outp = g_out + ((size_t)b * Lseq + c * CC + t) * Dd + jb;
#pragma unroll
    for (int r = 0; r < 8; r++) {
        float o = lmb[r] * acc[r];
        outp[r] = o * sigf(o);
    }
}

__global__ void __launch_bounds__(128) rms_kernel(const float* __restrict__ rmsw,
                                                  float* __restrict__ out) {
    int n = blockIdx.x;
    int d = threadIdx.x;
    int lane = d & 31, w = d >> 5;
    __shared__ float red[4];
    float v = g_ol[(size_t)n * Dd + d];
    float ss = warp_sum(v * v);
    if (lane == 0) red[w] = ss;
    __syncthreads();
    float mean = (red[0] + red[1] + red[2] + red[3]) * (1.f / 128.f);
    float s = rsqrtf(mean + 1e-6f);
    out[(size_t)n * Dd + d] = v * s * rmsw[d] + g_res[(size_t)n * Dd + d];
}

extern "C" void kernel_launch(void* const* d_in, const int* in_sizes, int n_in,
                              void* d_out, int out_size) {
    const float* x      = (const float*)d_in[0];
    const float* state  = (const float*)d_in[1];
    const float* W_in   = (const float*)d_in[2];
    const float* W_gate = (const float*)d_in[3];
    const float* W_out  = (const float*)d_in[4];
    const float* W_res  = (const float*)d_in[5];
    const float* qconvw = (const float*)d_in[6];
    const float* qconvb = (const float*)d_in[7];
    const float* kconvw = (const float*)d_in[8];
    const float* kconvb = (const float*)d_in[9];
    const float* rmsw   = (const float*)d_in[10];
    float* out = (float*)d_out;

    float *qkv, *gg, *res, *outs, *ol;
    cudaGetSymbolAddress((void**)&qkv,  g_qkv);
    cudaGetSymbolAddress((void**)&gg,   g_g);
    cudaGetSymbolAddress((void**)&res,  g_res);
    cudaGetSymbolAddress((void**)&outs, g_out);
    cudaGetSymbolAddress((void**)&ol,   g_ol);

    float* sfin = (out_size >= BLD + BDD) ? (out + BLD) : nullptr;

    const int oc_smem = (128 * 132 + 5 * 16 * 132 + 512) * 4;
    cudaFuncSetAttribute(outchunk_kernel, cudaFuncAttributeMaxDynamicSharedMemorySize,
                         oc_smem);
    const int seq_smem = 2 * SEQBUF * 4;
    cudaFuncSetAttribute(seq_kernel, cudaFuncAttributeMaxDynamicSharedMemorySize,
                         seq_smem);

    gemm_kernel<false><<<dim3(512 / 64, NROWS / 64), 256>>>(x, Dd, W_in, qkv, 512);
    gemm_kernel<true><<<dim3(256 / 64, NROWS / 64), 256>>>(qkv + 384, 512, W_gate, gg, 256);
    prep_kernel<<<NBC, 256>>>(qconvw, qconvb, kconvw, kconvb);
    seq_kernel<<<Bsz * 16, 256, seq_smem>>>(state, sfin);
    gemm_kernel<false><<<dim3(Dd / 64, NROWS / 64), 256>>>(x, Dd, W_res, res, Dd);
    outchunk_kernel<<<NBC, 256, oc_smem>>>();
    gemm_kernel<false><<<dim3(Dd / 64, NROWS / 64), 256>>>(outs, Dd, W_out, ol, Dd);
    rms_kernel<<<NROWS, 128>>>(rmsw, out);
}